// round 16
// baseline (speedup 1.0000x reference)
#include <cuda_runtime.h>
#include <cuda_fp16.h>
#include <cstdint>
#include <cstddef>

// ---------------- problem dims ----------------
#define NN 50000
#define FF 256
#define EE 200000
#define HH 4
#define CC 128
#define GG 256
#define NCLS 10
#define EPS 1e-16f

#define N1 2048
#define N2 1664
#define KMAX 512
#define NB 391             // ceil(NN/128)
#define BROWS (N1 + N2)
#define H0 25088           // first node half (196*128)
#define H1 (NN - H0)       // 24912

// ---------------- scratch (device globals) ----------------
__device__ __align__(256) __half g_qkvs1[(size_t)NN * N1];
__device__ __align__(256) __half g_qkvs2[(size_t)NN * N2];
__device__ __align__(256) __half g_A[(size_t)NN * KMAX];
__device__ __align__(256) __half g_B[(size_t)BROWS * KMAX];
__device__ __align__(256) float  g_h2[(size_t)NN * CC];
__device__ __align__(256) float  g_biasv[BROWS];
__device__ __align__(256) int    g_cnt[NN];
__device__ __align__(256) int    g_bsum[512];
__device__ __align__(256) int    g_rowptr[NN + 1];
__device__ __align__(256) int    g_cur[NN];
__device__ __align__(256) int    g_csrsrc[EE];

// ---------------- PTX helpers ----------------
__device__ __forceinline__ uint32_t smem_u32(const void* p) {
    uint32_t a;
    asm("{ .reg .u64 t; cvta.to.shared.u64 t, %1; cvt.u32.u64 %0, t; }" : "=r"(a) : "l"(p));
    return a;
}
__device__ __forceinline__ void cp16(uint32_t dst, const void* src, unsigned srcsz) {
    asm volatile("cp.async.cg.shared.global [%0], [%1], 16, %2;"
                 :: "r"(dst), "l"(src), "r"(srcsz) : "memory");
}
__device__ __forceinline__ void ldsm4(uint32_t& r0, uint32_t& r1, uint32_t& r2, uint32_t& r3,
                                      uint32_t a) {
    asm volatile("ldmatrix.sync.aligned.m8n8.x4.shared.b16 {%0,%1,%2,%3}, [%4];"
                 : "=r"(r0), "=r"(r1), "=r"(r2), "=r"(r3) : "r"(a));
}
__device__ __forceinline__ void mma_f16(float* c, const uint32_t* a, const uint32_t* b) {
    asm("mma.sync.aligned.m16n8k16.row.col.f32.f16.f16.f32 "
        "{%0,%1,%2,%3}, {%4,%5,%6,%7}, {%8,%9}, {%0,%1,%2,%3};"
        : "+f"(c[0]), "+f"(c[1]), "+f"(c[2]), "+f"(c[3])
        : "r"(a[0]), "r"(a[1]), "r"(a[2]), "r"(a[3]), "r"(b[0]), "r"(b[1]));
}

// ---------------- fp16 GEMM: 64x64 warp tiles, 4-stage (round-13 best) ------
#define TILE_B   (128 * 80)
#define STAGE_B  (2 * TILE_B)
#define SMEM_GEMM (4 * STAGE_B)           // 81920 B -> 2 CTAs/SM

__global__ __launch_bounds__(128, 2)
void gemm_f16(const __half* __restrict__ Ab, int lda, int K,
              const __half* __restrict__ Bb,
              const float* __restrict__ bias, __half* __restrict__ Cout, int ldo, int nrows)
{
    extern __shared__ char smem[];
    const uint32_t sb = smem_u32(smem);
    const int tid = threadIdx.x;
    const int lane = tid & 31;
    const int wid = tid >> 5;
    const int warpM = wid & 1;
    const int warpN = wid >> 1;
    const int rowBase = blockIdx.y * 128;
    const int colBase = blockIdx.x * 128;

    float acc[4][8][4];
#pragma unroll
    for (int i = 0; i < 4; i++)
#pragma unroll
        for (int j = 0; j < 8; j++)
#pragma unroll
            for (int f = 0; f < 4; f++) acc[i][j][f] = 0.f;

    const int T = K >> 5;

    auto loadStage = [&](int s, int k0) {
        uint32_t base = sb + s * STAGE_B;
#pragma unroll
        for (int t = 0; t < 4; t++) {
            int c = tid + t * 128;
            int r = c >> 2;
            int q = c & 3;
            uint32_t soff = (uint32_t)(r * 80 + q * 16);
            int ga = rowBase + r;
            unsigned va = (ga < nrows) ? 16u : 0u;
            int gac = (ga < nrows) ? ga : (nrows - 1);
            cp16(base + soff,          Ab + (size_t)gac * lda + k0 + q * 8, va);
            cp16(base + TILE_B + soff, Bb + (size_t)(colBase + r) * KMAX + k0 + q * 8, 16u);
        }
        asm volatile("cp.async.commit_group;" ::: "memory");
    };

    const uint32_t aOff = (uint32_t)((warpM * 64 + (lane & 15)) * 80 + (lane >> 4) * 16);
    const uint32_t bOff = (uint32_t)((warpN * 64 + (lane & 7) + ((lane >> 4) & 1) * 8) * 80
                                     + ((lane >> 3) & 1) * 16);

    loadStage(0, 0);
    loadStage(1, 32);

    for (int it = 0; it < T; it++) {
        if (it + 2 < T) loadStage((it + 2) & 3, (it + 2) << 5);
        int pend = ((it + 2 < T) ? 2 : (it + 1 < T) ? 1 : 0);
        if (pend == 2)      asm volatile("cp.async.wait_group 2;" ::: "memory");
        else if (pend == 1) asm volatile("cp.async.wait_group 1;" ::: "memory");
        else                asm volatile("cp.async.wait_group 0;" ::: "memory");
        __syncthreads();

        uint32_t tb = sb + (it & 3) * STAGE_B;
#pragma unroll
        for (int ks = 0; ks < 2; ks++) {
            uint32_t kb = ks * 32;
            uint32_t ah[4][4];
#pragma unroll
            for (int i = 0; i < 4; i++) {
                uint32_t ad = tb + aOff + i * (16 * 80) + kb;
                ldsm4(ah[i][0], ah[i][1], ah[i][2], ah[i][3], ad);
            }
#pragma unroll
            for (int j2 = 0; j2 < 4; j2++) {
                uint32_t bd = tb + TILE_B + bOff + j2 * (16 * 80) + kb;
                uint32_t b0[2], b1[2];
                ldsm4(b0[0], b0[1], b1[0], b1[1], bd);
#pragma unroll
                for (int i = 0; i < 4; i++) {
                    mma_f16(acc[i][j2 * 2 + 0], ah[i], b0);
                    mma_f16(acc[i][j2 * 2 + 1], ah[i], b1);
                }
            }
        }
    }

#pragma unroll
    for (int i = 0; i < 4; i++) {
        int r0 = rowBase + warpM * 64 + i * 16 + (lane >> 2);
#pragma unroll
        for (int rr = 0; rr < 2; rr++) {
            int grow = r0 + rr * 8;
            if (grow >= nrows) continue;
#pragma unroll
            for (int j = 0; j < 8; j++) {
                int gc = colBase + warpN * 64 + j * 8 + (lane & 3) * 2;
                __half2 o = __floats2half2_rn(acc[i][j][rr * 2 + 0] + bias[gc + 0],
                                              acc[i][j][rr * 2 + 1] + bias[gc + 1]);
                *reinterpret_cast<__half2*>(Cout + (size_t)grow * ldo + gc) = o;
            }
        }
    }
}

// ---------------- mega prep kernel ----------------
__global__ void prep(
    const float* __restrict__ Wq1, const float* __restrict__ bq1,
    const float* __restrict__ Wk1, const float* __restrict__ bk1,
    const float* __restrict__ Wv1, const float* __restrict__ bv1,
    const float* __restrict__ Ws1, const float* __restrict__ bs1,
    const float* __restrict__ Wq2, const float* __restrict__ bq2,
    const float* __restrict__ Wk2, const float* __restrict__ bk2,
    const float* __restrict__ Wv2, const float* __restrict__ bv2,
    const float* __restrict__ Ws2, const float* __restrict__ bs2,
    const float* __restrict__ x,
    __half* __restrict__ B, float* __restrict__ bias,
    __half* __restrict__ A, int* __restrict__ cnt)
{
    int task = blockIdx.z;
    int tx = threadIdx.x, ty = threadIdx.y;

    if (task == 8) {
        int bid = blockIdx.y * 16 + blockIdx.x;
        int tid = ty * 32 + tx;
        size_t start = (size_t)bid * 256 + tid;
        for (size_t i = start; i < (size_t)NN * FF; i += 65536)
            A[i] = __float2half_rn(x[i]);
        for (size_t i = start; i < NN; i += 65536)
            cnt[i] = 0;
        return;
    }

    const float *W, *b;
    int K, M, rowOff;
    switch (task) {
        case 0: W = Wq1; b = bq1; K = FF;  M = 512; rowOff = 0;    break;
        case 1: W = Wk1; b = bk1; K = FF;  M = 512; rowOff = 512;  break;
        case 2: W = Wv1; b = bv1; K = FF;  M = 512; rowOff = 1024; break;
        case 3: W = Ws1; b = bs1; K = FF;  M = 512; rowOff = 1536; break;
        case 4: W = Wq2; b = bq2; K = 512; M = 512; rowOff = 2048; break;
        case 5: W = Wk2; b = bk2; K = 512; M = 512; rowOff = 2560; break;
        case 6: W = Wv2; b = bv2; K = 512; M = 512; rowOff = 3072; break;
        default: W = Ws2; b = bs2; K = 512; M = 128; rowOff = 3584; break;
    }
    int nb = blockIdx.x * 32, kb = blockIdx.y * 32;
    if (nb >= M || kb >= K) return;

    __shared__ float tile[32][33];
#pragma unroll
    for (int i = 0; i < 4; i++)
        tile[ty + i * 8][tx] = W[(size_t)(kb + ty + i * 8) * M + nb + tx];
    __syncthreads();
#pragma unroll
    for (int i = 0; i < 4; i++)
        B[(size_t)(rowOff + nb + ty + i * 8) * KMAX + kb + tx] =
            __float2half_rn(tile[tx][ty + i * 8]);
    if (ty == 0 && blockIdx.y == 0) bias[rowOff + nb + tx] = b[nb + tx];
}

// ---------------- CSR build ----------------
__global__ void hist_dst(const int* __restrict__ ei, int* __restrict__ cnt) {
    int i = blockIdx.x * blockDim.x + threadIdx.x;
    if (i < EE) atomicAdd(&cnt[ei[EE + i]], 1);
}
__global__ void blocksum(const int* __restrict__ cnt, int* __restrict__ bsum) {
    __shared__ int sm[128];
    int idx = blockIdx.x * 128 + threadIdx.x;
    sm[threadIdx.x] = (idx < NN) ? cnt[idx] : 0;
    __syncthreads();
#pragma unroll
    for (int off = 64; off; off >>= 1) {
        if (threadIdx.x < off) sm[threadIdx.x] += sm[threadIdx.x + off];
        __syncthreads();
    }
    if (threadIdx.x == 0) bsum[blockIdx.x] = sm[0];
}
__global__ void write_rowptr(const int* __restrict__ cnt, const int* __restrict__ bsum,
                             int* __restrict__ rowptr, int* __restrict__ cur) {
    __shared__ int part[128];
    __shared__ int sm[128];
    int b = blockIdx.x, t = threadIdx.x;
    int a = 0;
    for (int i = t; i < b; i += 128) a += bsum[i];
    part[t] = a;
    __syncthreads();
#pragma unroll
    for (int off = 64; off; off >>= 1) {
        if (t < off) part[t] += part[t + off];
        __syncthreads();
    }
    int base = part[0];
    int idx = b * 128 + t;
    int v = (idx < NN) ? cnt[idx] : 0;
    sm[t] = v;
    __syncthreads();
#pragma unroll
    for (int off = 1; off < 128; off <<= 1) {
        int x = (t >= off) ? sm[t - off] : 0;
        __syncthreads();
        sm[t] += x;
        __syncthreads();
    }
    if (idx < NN) {
        int r = base + sm[t] - v;
        rowptr[idx] = r;
        cur[idx] = r;
        if (idx == NN - 1) rowptr[NN] = r + v;
    }
}
__global__ void fill_csr(const int* __restrict__ ei, int* __restrict__ cur,
                         int* __restrict__ csrsrc) {
    int i = blockIdx.x * blockDim.x + threadIdx.x;
    if (i >= EE) return;
    int pos = atomicAdd(&cur[ei[EE + i]], 1);
    csrsrc[pos] = ei[i];
}

// ---------------- fused attention: online softmax (verified) ----------------
__global__ __launch_bounds__(128) void att_fused(
    const __half* __restrict__ qkv, int stride, int qOff, int kOff, int vOff,
    const int* __restrict__ rowptr, const int* __restrict__ csrsrc,
    int skipOff, int mode,
    __half* __restrict__ Aout, float* __restrict__ h2, int nodeOff)
{
    int n = blockIdx.x + nodeOff;
    int h = threadIdx.x >> 5, lane = threadIdx.x & 31;
    int r0 = rowptr[n], r1 = rowptr[n + 1];
    const int hoff = h * CC + lane * 4;

    uint2 qraw = *reinterpret_cast<const uint2*>(qkv + (size_t)n * stride + qOff + hoff);
    float2 q01 = __half22float2(*reinterpret_cast<__half2*>(&qraw.x));
    float2 q23 = __half22float2(*reinterpret_cast<__half2*>(&qraw.y));

    float m = -3.0e38f, s = 0.f;
    float4 acc = make_float4(0.f, 0.f, 0.f, 0.f);
    for (int j = r0; j < r1; j++) {
        int src = csrsrc[j];
        const __half* base = qkv + (size_t)src * stride;
        uint2 kraw = *reinterpret_cast<const uint2*>(base + kOff + hoff);
        uint2 vraw = *reinterpret_cast<const uint2*>(base + vOff + hoff);
        float2 k01 = __half22float2(*reinterpret_cast<__half2*>(&kraw.x));
        float2 k23 = __half22float2(*reinterpret_cast<__half2*>(&kraw.y));
        float d = q01.x * k01.x + q01.y * k01.y + q23.x * k23.x + q23.y * k23.y;
#pragma unroll
        for (int o = 16; o; o >>= 1) d += __shfl_xor_sync(0xFFFFFFFFu, d, o);
        d *= 0.08838834764831845f;
        float mn = fmaxf(m, d);
        float corr = __expf(m - mn);
        float p = __expf(d - mn);
        float2 v01 = __half22float2(*reinterpret_cast<__half2*>(&vraw.x));
        float2 v23 = __half22float2(*reinterpret_cast<__half2*>(&vraw.y));
        s = s * corr + p;
        acc.x = acc.x * corr + p * v01.x;
        acc.y = acc.y * corr + p * v01.y;
        acc.z = acc.z * corr + p * v23.x;
        acc.w = acc.w * corr + p * v23.y;
        m = mn;
    }
    float inv = 1.f / (s + EPS);

    if (mode == 0) {
        uint2 sraw = *reinterpret_cast<const uint2*>(qkv + (size_t)n * stride + skipOff + hoff);
        float2 s01 = __half22float2(*reinterpret_cast<__half2*>(&sraw.x));
        float2 s23 = __half22float2(*reinterpret_cast<__half2*>(&sraw.y));
        float v[4];
        v[0] = s01.x + acc.x * inv; v[1] = s01.y + acc.y * inv;
        v[2] = s23.x + acc.z * inv; v[3] = s23.y + acc.w * inv;
#pragma unroll
        for (int u = 0; u < 4; u++) v[u] = v[u] > 0.f ? v[u] : expm1f(v[u]);  // ELU
        __half2* op = reinterpret_cast<__half2*>(Aout + (size_t)n * KMAX + hoff);
        op[0] = __floats2half2_rn(v[0], v[1]);
        op[1] = __floats2half2_rn(v[2], v[3]);
    } else {
        __shared__ float sm[HH][CC];
        float qsc = inv * 0.25f;
        sm[h][lane * 4 + 0] = acc.x * qsc;
        sm[h][lane * 4 + 1] = acc.y * qsc;
        sm[h][lane * 4 + 2] = acc.z * qsc;
        sm[h][lane * 4 + 3] = acc.w * qsc;
        __syncthreads();
        int c = threadIdx.x;
        float val = sm[0][c] + sm[1][c] + sm[2][c] + sm[3][c];
        float sk = __half2float(qkv[(size_t)n * stride + skipOff + c]);
        float r = sk + val;
        h2[(size_t)n * CC + c] = r > 0.f ? r : expm1f(r);   // fused ELU
    }
}

// ---------------- fused pooling + classifier head ----------------
__global__ __launch_bounds__(128) void poolhead(
    const float* __restrict__ h2, const int* __restrict__ batch,
    const float* __restrict__ Wfc, const float* __restrict__ bfc,
    float* __restrict__ out)
{
    int g = blockIdx.x, t = threadIdx.x;
    __shared__ int ss[2];
    if (t < 2) {
        int target = g + t;
        int lo = 0, hi = NN;
        while (lo < hi) {
            int mid = (lo + hi) >> 1;
            if (batch[mid] < target) lo = mid + 1; else hi = mid;
        }
        ss[t] = lo;
    }
    __syncthreads();
    int s0 = ss[0], s1 = ss[1];

    float sum0 = 0.f, sum1 = 0.f, sum2 = 0.f, sum3 = 0.f;
    int i = s0;
    for (; i + 3 < s1; i += 4) {
        sum0 += h2[(size_t)(i + 0) * CC + t];
        sum1 += h2[(size_t)(i + 1) * CC + t];
        sum2 += h2[(size_t)(i + 2) * CC + t];
        sum3 += h2[(size_t)(i + 3) * CC + t];
    }
    for (; i < s1; i++) sum0 += h2[(size_t)i * CC + t];
    float sum = (sum0 + sum1) + (sum2 + sum3);
    float cv = fmaxf((float)(s1 - s0), 1.f);

    __shared__ float sm[CC];
    __shared__ float logits[NCLS];
    sm[t] = sum / cv;
    __syncthreads();
    if (t < NCLS) {
        float acc = bfc[t];
#pragma unroll 4
        for (int c = 0; c < CC; c++) acc += sm[c] * Wfc[c * NCLS + t];
        logits[t] = acc;
    }
    __syncthreads();
    if (t == 0) {
        float mx = -1e30f;
#pragma unroll
        for (int j = 0; j < NCLS; j++) mx = fmaxf(mx, logits[j]);
        float ssum = 0.f;
#pragma unroll
        for (int j = 0; j < NCLS; j++) ssum += expf(logits[j] - mx);
        float lse = mx + logf(ssum);
#pragma unroll
        for (int j = 0; j < NCLS; j++) out[g * NCLS + j] = logits[j] - lse;
    }
}

// ---------------- launch (multi-stream graph with fork/join) ----------------
extern "C" void kernel_launch(void* const* d_in, const int* in_sizes, int n_in,
                              void* d_out, int out_size)
{
    const float* x     = (const float*)d_in[0];
    const int*   ei    = (const int*)d_in[1];
    const int*   batch = (const int*)d_in[2];
    const float* Wq1 = (const float*)d_in[3];  const float* bq1 = (const float*)d_in[4];
    const float* Wk1 = (const float*)d_in[5];  const float* bk1 = (const float*)d_in[6];
    const float* Wv1 = (const float*)d_in[7];  const float* bv1 = (const float*)d_in[8];
    const float* Ws1 = (const float*)d_in[9];  const float* bs1 = (const float*)d_in[10];
    const float* Wq2 = (const float*)d_in[11]; const float* bq2 = (const float*)d_in[12];
    const float* Wk2 = (const float*)d_in[13]; const float* bk2 = (const float*)d_in[14];
    const float* Wv2 = (const float*)d_in[15]; const float* bv2 = (const float*)d_in[16];
    const float* Ws2 = (const float*)d_in[17]; const float* bs2 = (const float*)d_in[18];
    const float* Wfc = (const float*)d_in[19]; const float* bfc = (const float*)d_in[20];
    float* out = (float*)d_out;

    __half *qkvs1, *qkvs2, *A, *B;
    float *bias, *h2;
    int *cnt, *bsum, *rowptr, *cur, *csrsrc;
    cudaGetSymbolAddress((void**)&qkvs1, g_qkvs1);
    cudaGetSymbolAddress((void**)&qkvs2, g_qkvs2);
    cudaGetSymbolAddress((void**)&A, g_A);
    cudaGetSymbolAddress((void**)&B, g_B);
    cudaGetSymbolAddress((void**)&h2, g_h2);
    cudaGetSymbolAddress((void**)&bias, g_biasv);
    cudaGetSymbolAddress((void**)&cnt, g_cnt);
    cudaGetSymbolAddress((void**)&bsum, g_bsum);
    cudaGetSymbolAddress((void**)&rowptr, g_rowptr);
    cudaGetSymbolAddress((void**)&cur, g_cur);
    cudaGetSymbolAddress((void**)&csrsrc, g_csrsrc);

    cudaFuncSetAttribute(gemm_f16, cudaFuncAttributeMaxDynamicSharedMemorySize, SMEM_GEMM);

    // side stream + events (created per call; no static guards, no device mem)
    cudaStream_t s1;
    cudaStreamCreateWithFlags(&s1, cudaStreamNonBlocking);
    cudaEvent_t evPrep, evCsr, evA0, evA1, evG2;
    cudaEventCreateWithFlags(&evPrep, cudaEventDisableTiming);
    cudaEventCreateWithFlags(&evCsr,  cudaEventDisableTiming);
    cudaEventCreateWithFlags(&evA0,   cudaEventDisableTiming);
    cudaEventCreateWithFlags(&evA1,   cudaEventDisableTiming);
    cudaEventCreateWithFlags(&evG2,   cudaEventDisableTiming);

    // 1) prep on main stream
    prep<<<dim3(16, 16, 9), dim3(32, 8)>>>(
        Wq1, bq1, Wk1, bk1, Wv1, bv1, Ws1, bs1,
        Wq2, bq2, Wk2, bk2, Wv2, bv2, Ws2, bs2,
        x, B, bias, A, cnt);
    cudaEventRecord(evPrep, 0);

    // fork: CSR chain on s1, concurrent with gemm1 on main
    cudaStreamWaitEvent(s1, evPrep, 0);
    hist_dst<<<(EE + 255) / 256, 256, 0, s1>>>(ei, cnt);
    blocksum<<<NB, 128, 0, s1>>>(cnt, bsum);
    write_rowptr<<<NB, 128, 0, s1>>>(cnt, bsum, rowptr, cur);
    fill_csr<<<(EE + 255) / 256, 256, 0, s1>>>(ei, cur, csrsrc);
    cudaEventRecord(evCsr, s1);

    // gemm1 on main stream (runs concurrent with CSR)
    gemm_f16<<<dim3(N1 / 128, NB), 128, SMEM_GEMM>>>(
        A, FF, FF, B, bias, qkvs1, N1, NN);

    // att1 needs CSR + gemm1
    cudaStreamWaitEvent(0, evCsr, 0);
    att_fused<<<H0, 128>>>(qkvs1, N1, 0, 512, 1024, rowptr, csrsrc,
                           1536, 0, A, nullptr, 0);
    cudaEventRecord(evA0, 0);
    att_fused<<<H1, 128>>>(qkvs1, N1, 0, 512, 1024, rowptr, csrsrc,
                           1536, 0, A, nullptr, H0);
    cudaEventRecord(evA1, 0);

    // gemm2 halves on s1: h0 runs concurrent with att1_h1 (disjoint A rows)
    cudaStreamWaitEvent(s1, evA0, 0);
    gemm_f16<<<dim3(N2 / 128, H0 / 128), 128, SMEM_GEMM, s1>>>(
        A, 512, 512, B + (size_t)N1 * KMAX, bias + N1, qkvs2, N2, H0);
    cudaStreamWaitEvent(s1, evA1, 0);
    gemm_f16<<<dim3(N2 / 128, (H1 + 127) / 128), 128, SMEM_GEMM, s1>>>(
        A + (size_t)H0 * 512, 512, 512, B + (size_t)N1 * KMAX, bias + N1,
        qkvs2 + (size_t)H0 * N2, N2, H1);
    cudaEventRecord(evG2, s1);

    // join back to main stream: att2 + poolhead
    cudaStreamWaitEvent(0, evG2, 0);
    att_fused<<<NN, 128>>>(qkvs2, N2, 0, 512, 1024, rowptr, csrsrc,
                           1536, 1, nullptr, h2, 0);
    poolhead<<<GG, 128>>>(h2, batch, Wfc, bfc, out);
}

// round 17
// speedup vs baseline: 1.0295x; 1.0295x over previous
#include <cuda_runtime.h>
#include <cuda_fp16.h>
#include <cstdint>
#include <cstddef>

// ---------------- problem dims ----------------
#define NN 50000
#define FF 256
#define EE 200000
#define HH 4
#define CC 128
#define GG 256
#define NCLS 10
#define EPS 1e-16f

#define N1 2048
#define N2 1664
#define KMAX 512
#define NB 391             // ceil(NN/128)
#define BROWS (N1 + N2)

// ---------------- scratch (device globals) ----------------
__device__ __align__(256) __half g_qkvs1[(size_t)NN * N1];
__device__ __align__(256) __half g_qkvs2[(size_t)NN * N2];
__device__ __align__(256) __half g_A[(size_t)NN * KMAX];
__device__ __align__(256) __half g_B[(size_t)BROWS * KMAX];
__device__ __align__(256) float  g_h2[(size_t)NN * CC];
__device__ __align__(256) float  g_biasv[BROWS];
__device__ __align__(256) int    g_cnt[NN];
__device__ __align__(256) int    g_bsum[512];
__device__ __align__(256) int    g_rowptr[NN + 1];
__device__ __align__(256) int    g_cur[NN];
__device__ __align__(256) int    g_csrsrc[EE];

// ---------------- PTX helpers ----------------
__device__ __forceinline__ uint32_t smem_u32(const void* p) {
    uint32_t a;
    asm("{ .reg .u64 t; cvta.to.shared.u64 t, %1; cvt.u32.u64 %0, t; }" : "=r"(a) : "l"(p));
    return a;
}
__device__ __forceinline__ void cp16(uint32_t dst, const void* src, unsigned srcsz) {
    asm volatile("cp.async.cg.shared.global [%0], [%1], 16, %2;"
                 :: "r"(dst), "l"(src), "r"(srcsz) : "memory");
}
__device__ __forceinline__ void ldsm4(uint32_t& r0, uint32_t& r1, uint32_t& r2, uint32_t& r3,
                                      uint32_t a) {
    asm volatile("ldmatrix.sync.aligned.m8n8.x4.shared.b16 {%0,%1,%2,%3}, [%4];"
                 : "=r"(r0), "=r"(r1), "=r"(r2), "=r"(r3) : "r"(a));
}
__device__ __forceinline__ void mma_f16(float* c, const uint32_t* a, const uint32_t* b) {
    asm("mma.sync.aligned.m16n8k16.row.col.f32.f16.f16.f32 "
        "{%0,%1,%2,%3}, {%4,%5,%6,%7}, {%8,%9}, {%0,%1,%2,%3};"
        : "+f"(c[0]), "+f"(c[1]), "+f"(c[2]), "+f"(c[3])
        : "r"(a[0]), "r"(a[1]), "r"(a[2]), "r"(a[3]), "r"(b[0]), "r"(b[1]));
}

// ---------------- fp16 GEMM: 64x64 warp tiles, 4-stage (round-13 verified) --
#define TILE_B   (128 * 80)
#define STAGE_B  (2 * TILE_B)
#define SMEM_GEMM (4 * STAGE_B)           // 81920 B -> 2 CTAs/SM

__global__ __launch_bounds__(128, 2)
void gemm_f16(const __half* __restrict__ Ab, int lda, int K,
              const __half* __restrict__ Bb,
              const float* __restrict__ bias, __half* __restrict__ Cout, int ldo, int nrows)
{
    extern __shared__ char smem[];
    const uint32_t sb = smem_u32(smem);
    const int tid = threadIdx.x;
    const int lane = tid & 31;
    const int wid = tid >> 5;
    const int warpM = wid & 1;
    const int warpN = wid >> 1;
    const int rowBase = blockIdx.y * 128;
    const int colBase = blockIdx.x * 128;

    float acc[4][8][4];
#pragma unroll
    for (int i = 0; i < 4; i++)
#pragma unroll
        for (int j = 0; j < 8; j++)
#pragma unroll
            for (int f = 0; f < 4; f++) acc[i][j][f] = 0.f;

    const int T = K >> 5;

    auto loadStage = [&](int s, int k0) {
        uint32_t base = sb + s * STAGE_B;
#pragma unroll
        for (int t = 0; t < 4; t++) {
            int c = tid + t * 128;
            int r = c >> 2;
            int q = c & 3;
            uint32_t soff = (uint32_t)(r * 80 + q * 16);
            int ga = rowBase + r;
            unsigned va = (ga < nrows) ? 16u : 0u;
            int gac = (ga < nrows) ? ga : (nrows - 1);
            cp16(base + soff,          Ab + (size_t)gac * lda + k0 + q * 8, va);
            cp16(base + TILE_B + soff, Bb + (size_t)(colBase + r) * KMAX + k0 + q * 8, 16u);
        }
        asm volatile("cp.async.commit_group;" ::: "memory");
    };

    const uint32_t aOff = (uint32_t)((warpM * 64 + (lane & 15)) * 80 + (lane >> 4) * 16);
    const uint32_t bOff = (uint32_t)((warpN * 64 + (lane & 7) + ((lane >> 4) & 1) * 8) * 80
                                     + ((lane >> 3) & 1) * 16);

    loadStage(0, 0);
    loadStage(1, 32);

    for (int it = 0; it < T; it++) {
        if (it + 2 < T) loadStage((it + 2) & 3, (it + 2) << 5);
        int pend = ((it + 2 < T) ? 2 : (it + 1 < T) ? 1 : 0);
        if (pend == 2)      asm volatile("cp.async.wait_group 2;" ::: "memory");
        else if (pend == 1) asm volatile("cp.async.wait_group 1;" ::: "memory");
        else                asm volatile("cp.async.wait_group 0;" ::: "memory");
        __syncthreads();

        uint32_t tb = sb + (it & 3) * STAGE_B;
#pragma unroll
        for (int ks = 0; ks < 2; ks++) {
            uint32_t kb = ks * 32;
            uint32_t ah[4][4];
#pragma unroll
            for (int i = 0; i < 4; i++) {
                uint32_t ad = tb + aOff + i * (16 * 80) + kb;
                ldsm4(ah[i][0], ah[i][1], ah[i][2], ah[i][3], ad);
            }
#pragma unroll
            for (int j2 = 0; j2 < 4; j2++) {
                uint32_t bd = tb + TILE_B + bOff + j2 * (16 * 80) + kb;
                uint32_t b0[2], b1[2];
                ldsm4(b0[0], b0[1], b1[0], b1[1], bd);
#pragma unroll
                for (int i = 0; i < 4; i++) {
                    mma_f16(acc[i][j2 * 2 + 0], ah[i], b0);
                    mma_f16(acc[i][j2 * 2 + 1], ah[i], b1);
                }
            }
        }
    }

#pragma unroll
    for (int i = 0; i < 4; i++) {
        int r0 = rowBase + warpM * 64 + i * 16 + (lane >> 2);
#pragma unroll
        for (int rr = 0; rr < 2; rr++) {
            int grow = r0 + rr * 8;
            if (grow >= nrows) continue;
#pragma unroll
            for (int j = 0; j < 8; j++) {
                int gc = colBase + warpN * 64 + j * 8 + (lane & 3) * 2;
                __half2 o = __floats2half2_rn(acc[i][j][rr * 2 + 0] + bias[gc + 0],
                                              acc[i][j][rr * 2 + 1] + bias[gc + 1]);
                *reinterpret_cast<__half2*>(Cout + (size_t)grow * ldo + gc) = o;
            }
        }
    }
}

// ---------------- mega prep kernel ----------------
__global__ void prep(
    const float* __restrict__ Wq1, const float* __restrict__ bq1,
    const float* __restrict__ Wk1, const float* __restrict__ bk1,
    const float* __restrict__ Wv1, const float* __restrict__ bv1,
    const float* __restrict__ Ws1, const float* __restrict__ bs1,
    const float* __restrict__ Wq2, const float* __restrict__ bq2,
    const float* __restrict__ Wk2, const float* __restrict__ bk2,
    const float* __restrict__ Wv2, const float* __restrict__ bv2,
    const float* __restrict__ Ws2, const float* __restrict__ bs2,
    const float* __restrict__ x,
    __half* __restrict__ B, float* __restrict__ bias,
    __half* __restrict__ A, int* __restrict__ cnt)
{
    int task = blockIdx.z;
    int tx = threadIdx.x, ty = threadIdx.y;

    if (task == 8) {
        int bid = blockIdx.y * 16 + blockIdx.x;
        int tid = ty * 32 + tx;
        size_t start = (size_t)bid * 256 + tid;
        for (size_t i = start; i < (size_t)NN * FF; i += 65536)
            A[i] = __float2half_rn(x[i]);
        for (size_t i = start; i < NN; i += 65536)
            cnt[i] = 0;
        return;
    }

    const float *W, *b;
    int K, M, rowOff;
    switch (task) {
        case 0: W = Wq1; b = bq1; K = FF;  M = 512; rowOff = 0;    break;
        case 1: W = Wk1; b = bk1; K = FF;  M = 512; rowOff = 512;  break;
        case 2: W = Wv1; b = bv1; K = FF;  M = 512; rowOff = 1024; break;
        case 3: W = Ws1; b = bs1; K = FF;  M = 512; rowOff = 1536; break;
        case 4: W = Wq2; b = bq2; K = 512; M = 512; rowOff = 2048; break;
        case 5: W = Wk2; b = bk2; K = 512; M = 512; rowOff = 2560; break;
        case 6: W = Wv2; b = bv2; K = 512; M = 512; rowOff = 3072; break;
        default: W = Ws2; b = bs2; K = 512; M = 128; rowOff = 3584; break;
    }
    int nb = blockIdx.x * 32, kb = blockIdx.y * 32;
    if (nb >= M || kb >= K) return;

    __shared__ float tile[32][33];
#pragma unroll
    for (int i = 0; i < 4; i++)
        tile[ty + i * 8][tx] = W[(size_t)(kb + ty + i * 8) * M + nb + tx];
    __syncthreads();
#pragma unroll
    for (int i = 0; i < 4; i++)
        B[(size_t)(rowOff + nb + ty + i * 8) * KMAX + kb + tx] =
            __float2half_rn(tile[tx][ty + i * 8]);
    if (ty == 0 && blockIdx.y == 0) bias[rowOff + nb + tx] = b[nb + tx];
}

// ---------------- CSR build ----------------
__global__ void hist_dst(const int* __restrict__ ei, int* __restrict__ cnt) {
    int i = blockIdx.x * blockDim.x + threadIdx.x;
    if (i < EE) atomicAdd(&cnt[ei[EE + i]], 1);
}
__global__ void blocksum(const int* __restrict__ cnt, int* __restrict__ bsum) {
    __shared__ int sm[128];
    int idx = blockIdx.x * 128 + threadIdx.x;
    sm[threadIdx.x] = (idx < NN) ? cnt[idx] : 0;
    __syncthreads();
#pragma unroll
    for (int off = 64; off; off >>= 1) {
        if (threadIdx.x < off) sm[threadIdx.x] += sm[threadIdx.x + off];
        __syncthreads();
    }
    if (threadIdx.x == 0) bsum[blockIdx.x] = sm[0];
}
__global__ void write_rowptr(const int* __restrict__ cnt, const int* __restrict__ bsum,
                             int* __restrict__ rowptr, int* __restrict__ cur) {
    __shared__ int part[128];
    __shared__ int sm[128];
    int b = blockIdx.x, t = threadIdx.x;
    int a = 0;
    for (int i = t; i < b; i += 128) a += bsum[i];
    part[t] = a;
    __syncthreads();
#pragma unroll
    for (int off = 64; off; off >>= 1) {
        if (t < off) part[t] += part[t + off];
        __syncthreads();
    }
    int base = part[0];
    int idx = b * 128 + t;
    int v = (idx < NN) ? cnt[idx] : 0;
    sm[t] = v;
    __syncthreads();
#pragma unroll
    for (int off = 1; off < 128; off <<= 1) {
        int x = (t >= off) ? sm[t - off] : 0;
        __syncthreads();
        sm[t] += x;
        __syncthreads();
    }
    if (idx < NN) {
        int r = base + sm[t] - v;
        rowptr[idx] = r;
        cur[idx] = r;
        if (idx == NN - 1) rowptr[NN] = r + v;
    }
}
__global__ void fill_csr(const int* __restrict__ ei, int* __restrict__ cur,
                         int* __restrict__ csrsrc) {
    int i = blockIdx.x * blockDim.x + threadIdx.x;
    if (i >= EE) return;
    int pos = atomicAdd(&cur[ei[EE + i]], 1);
    csrsrc[pos] = ei[i];
}

// ---------------- fused attention: online softmax (verified) ----------------
__global__ __launch_bounds__(128) void att_fused(
    const __half* __restrict__ qkv, int stride, int qOff, int kOff, int vOff,
    const int* __restrict__ rowptr, const int* __restrict__ csrsrc,
    int skipOff, int mode,
    __half* __restrict__ Aout, float* __restrict__ h2)
{
    int n = blockIdx.x;
    int h = threadIdx.x >> 5, lane = threadIdx.x & 31;
    int r0 = rowptr[n], r1 = rowptr[n + 1];
    const int hoff = h * CC + lane * 4;

    uint2 qraw = *reinterpret_cast<const uint2*>(qkv + (size_t)n * stride + qOff + hoff);
    float2 q01 = __half22float2(*reinterpret_cast<__half2*>(&qraw.x));
    float2 q23 = __half22float2(*reinterpret_cast<__half2*>(&qraw.y));

    float m = -3.0e38f, s = 0.f;
    float4 acc = make_float4(0.f, 0.f, 0.f, 0.f);
    for (int j = r0; j < r1; j++) {
        int src = csrsrc[j];
        const __half* base = qkv + (size_t)src * stride;
        uint2 kraw = *reinterpret_cast<const uint2*>(base + kOff + hoff);
        uint2 vraw = *reinterpret_cast<const uint2*>(base + vOff + hoff);
        float2 k01 = __half22float2(*reinterpret_cast<__half2*>(&kraw.x));
        float2 k23 = __half22float2(*reinterpret_cast<__half2*>(&kraw.y));
        float d = q01.x * k01.x + q01.y * k01.y + q23.x * k23.x + q23.y * k23.y;
#pragma unroll
        for (int o = 16; o; o >>= 1) d += __shfl_xor_sync(0xFFFFFFFFu, d, o);
        d *= 0.08838834764831845f;
        float mn = fmaxf(m, d);
        float corr = __expf(m - mn);
        float p = __expf(d - mn);
        float2 v01 = __half22float2(*reinterpret_cast<__half2*>(&vraw.x));
        float2 v23 = __half22float2(*reinterpret_cast<__half2*>(&vraw.y));
        s = s * corr + p;
        acc.x = acc.x * corr + p * v01.x;
        acc.y = acc.y * corr + p * v01.y;
        acc.z = acc.z * corr + p * v23.x;
        acc.w = acc.w * corr + p * v23.y;
        m = mn;
    }
    float inv = 1.f / (s + EPS);

    if (mode == 0) {
        uint2 sraw = *reinterpret_cast<const uint2*>(qkv + (size_t)n * stride + skipOff + hoff);
        float2 s01 = __half22float2(*reinterpret_cast<__half2*>(&sraw.x));
        float2 s23 = __half22float2(*reinterpret_cast<__half2*>(&sraw.y));
        float v[4];
        v[0] = s01.x + acc.x * inv; v[1] = s01.y + acc.y * inv;
        v[2] = s23.x + acc.z * inv; v[3] = s23.y + acc.w * inv;
#pragma unroll
        for (int u = 0; u < 4; u++) v[u] = v[u] > 0.f ? v[u] : expm1f(v[u]);  // ELU
        __half2* op = reinterpret_cast<__half2*>(Aout + (size_t)n * KMAX + hoff);
        op[0] = __floats2half2_rn(v[0], v[1]);
        op[1] = __floats2half2_rn(v[2], v[3]);
    } else {
        __shared__ float sm[HH][CC];
        float qsc = inv * 0.25f;
        sm[h][lane * 4 + 0] = acc.x * qsc;
        sm[h][lane * 4 + 1] = acc.y * qsc;
        sm[h][lane * 4 + 2] = acc.z * qsc;
        sm[h][lane * 4 + 3] = acc.w * qsc;
        __syncthreads();
        int c = threadIdx.x;
        float val = sm[0][c] + sm[1][c] + sm[2][c] + sm[3][c];
        float sk = __half2float(qkv[(size_t)n * stride + skipOff + c]);
        float r = sk + val;
        h2[(size_t)n * CC + c] = r > 0.f ? r : expm1f(r);   // fused ELU
    }
}

// ---------------- fused pooling + classifier head ----------------
__global__ __launch_bounds__(128) void poolhead(
    const float* __restrict__ h2, const int* __restrict__ batch,
    const float* __restrict__ Wfc, const float* __restrict__ bfc,
    float* __restrict__ out)
{
    int g = blockIdx.x, t = threadIdx.x;
    __shared__ int ss[2];
    if (t < 2) {
        int target = g + t;
        int lo = 0, hi = NN;
        while (lo < hi) {
            int mid = (lo + hi) >> 1;
            if (batch[mid] < target) lo = mid + 1; else hi = mid;
        }
        ss[t] = lo;
    }
    __syncthreads();
    int s0 = ss[0], s1 = ss[1];

    float sum0 = 0.f, sum1 = 0.f, sum2 = 0.f, sum3 = 0.f;
    int i = s0;
    for (; i + 3 < s1; i += 4) {
        sum0 += h2[(size_t)(i + 0) * CC + t];
        sum1 += h2[(size_t)(i + 1) * CC + t];
        sum2 += h2[(size_t)(i + 2) * CC + t];
        sum3 += h2[(size_t)(i + 3) * CC + t];
    }
    for (; i < s1; i++) sum0 += h2[(size_t)i * CC + t];
    float sum = (sum0 + sum1) + (sum2 + sum3);
    float cv = fmaxf((float)(s1 - s0), 1.f);

    __shared__ float sm[CC];
    __shared__ float logits[NCLS];
    sm[t] = sum / cv;
    __syncthreads();
    if (t < NCLS) {
        float acc = bfc[t];
#pragma unroll 4
        for (int c = 0; c < CC; c++) acc += sm[c] * Wfc[c * NCLS + t];
        logits[t] = acc;
    }
    __syncthreads();
    if (t == 0) {
        float mx = -1e30f;
#pragma unroll
        for (int j = 0; j < NCLS; j++) mx = fmaxf(mx, logits[j]);
        float ssum = 0.f;
#pragma unroll
        for (int j = 0; j < NCLS; j++) ssum += expf(logits[j] - mx);
        float lse = mx + logf(ssum);
#pragma unroll
        for (int j = 0; j < NCLS; j++) out[g * NCLS + j] = logits[j] - lse;
    }
}

// ---------------- launch: serial round-13 order + CSR || gemm1 fork only ----
extern "C" void kernel_launch(void* const* d_in, const int* in_sizes, int n_in,
                              void* d_out, int out_size)
{
    const float* x     = (const float*)d_in[0];
    const int*   ei    = (const int*)d_in[1];
    const int*   batch = (const int*)d_in[2];
    const float* Wq1 = (const float*)d_in[3];  const float* bq1 = (const float*)d_in[4];
    const float* Wk1 = (const float*)d_in[5];  const float* bk1 = (const float*)d_in[6];
    const float* Wv1 = (const float*)d_in[7];  const float* bv1 = (const float*)d_in[8];
    const float* Ws1 = (const float*)d_in[9];  const float* bs1 = (const float*)d_in[10];
    const float* Wq2 = (const float*)d_in[11]; const float* bq2 = (const float*)d_in[12];
    const float* Wk2 = (const float*)d_in[13]; const float* bk2 = (const float*)d_in[14];
    const float* Wv2 = (const float*)d_in[15]; const float* bv2 = (const float*)d_in[16];
    const float* Ws2 = (const float*)d_in[17]; const float* bs2 = (const float*)d_in[18];
    const float* Wfc = (const float*)d_in[19]; const float* bfc = (const float*)d_in[20];
    float* out = (float*)d_out;

    __half *qkvs1, *qkvs2, *A, *B;
    float *bias, *h2;
    int *cnt, *bsum, *rowptr, *cur, *csrsrc;
    cudaGetSymbolAddress((void**)&qkvs1, g_qkvs1);
    cudaGetSymbolAddress((void**)&qkvs2, g_qkvs2);
    cudaGetSymbolAddress((void**)&A, g_A);
    cudaGetSymbolAddress((void**)&B, g_B);
    cudaGetSymbolAddress((void**)&h2, g_h2);
    cudaGetSymbolAddress((void**)&bias, g_biasv);
    cudaGetSymbolAddress((void**)&cnt, g_cnt);
    cudaGetSymbolAddress((void**)&bsum, g_bsum);
    cudaGetSymbolAddress((void**)&rowptr, g_rowptr);
    cudaGetSymbolAddress((void**)&cur, g_cur);
    cudaGetSymbolAddress((void**)&csrsrc, g_csrsrc);

    cudaFuncSetAttribute(gemm_f16, cudaFuncAttributeMaxDynamicSharedMemorySize, SMEM_GEMM);

    cudaStream_t s1;
    cudaStreamCreateWithFlags(&s1, cudaStreamNonBlocking);
    cudaEvent_t evPrep, evCsr;
    cudaEventCreateWithFlags(&evPrep, cudaEventDisableTiming);
    cudaEventCreateWithFlags(&evCsr,  cudaEventDisableTiming);

    // 1) prep on main stream
    prep<<<dim3(16, 16, 9), dim3(32, 8)>>>(
        Wq1, bq1, Wk1, bk1, Wv1, bv1, Ws1, bs1,
        Wq2, bq2, Wk2, bk2, Wv2, bv2, Ws2, bs2,
        x, B, bias, A, cnt);
    cudaEventRecord(evPrep, 0);

    // fork: CSR chain on s1 (fills gemm1's tail waves)
    cudaStreamWaitEvent(s1, evPrep, 0);
    hist_dst<<<(EE + 255) / 256, 256, 0, s1>>>(ei, cnt);
    blocksum<<<NB, 128, 0, s1>>>(cnt, bsum);
    write_rowptr<<<NB, 128, 0, s1>>>(cnt, bsum, rowptr, cur);
    fill_csr<<<(EE + 255) / 256, 256, 0, s1>>>(ei, cur, csrsrc);
    cudaEventRecord(evCsr, s1);

    // gemm1 on main stream, concurrent with CSR
    gemm_f16<<<dim3(N1 / 128, NB), 128, SMEM_GEMM>>>(
        A, FF, FF, B, bias, qkvs1, N1, NN);

    // join: att1 needs CSR + gemm1
    cudaStreamWaitEvent(0, evCsr, 0);
    att_fused<<<NN, 128>>>(qkvs1, N1, 0, 512, 1024, rowptr, csrsrc,
                           1536, 0, A, nullptr);

    // layer 2: GEMM + attention (mean + skip + ELU fused)
    gemm_f16<<<dim3(N2 / 128, NB), 128, SMEM_GEMM>>>(
        A, 512, 512, B + (size_t)N1 * KMAX, bias + N1, qkvs2, N2, NN);
    att_fused<<<NN, 128>>>(qkvs2, N2, 0, 512, 1024, rowptr, csrsrc,
                           1536, 1, nullptr, h2);

    // fused mean-pool + FC + log_softmax
    poolhead<<<GG, 128>>>(h2, batch, Wfc, bfc, out);
}